// round 9
// baseline (speedup 1.0000x reference)
#include <cuda_runtime.h>
#include <math.h>
#include <stdint.h>

#define B_   2
#define S_   2048
#define H_   16
#define DH_  64
#define D_   1024
#define HID_ 4096
#define M_   (B_*S_)        // 4096 tokens
#define NROWS_ (B_*H_*S_)   // 65536 attn rows

// ---------------- scratch (static device globals; no runtime alloc) ----------
__device__ float g_q  [(size_t)M_*D_];   // q hi
__device__ float g_k  [(size_t)M_*D_];   // k hi
__device__ float g_qlo[(size_t)M_*D_];
__device__ float g_klo[(size_t)M_*D_];
__device__ float g_v  [(size_t)M_*D_];
__device__ float g_ao [(size_t)M_*D_];
__device__ float g_t1 [(size_t)M_*D_];
__device__ float g_h  [(size_t)M_*D_];
__device__ float g_hid[(size_t)M_*HID_];
__device__ float g_psum[(size_t)NROWS_*16];
__device__ float g_inv [(size_t)NROWS_];
// tf32-rounded copies of raw inputs
__device__ float g_xr [(size_t)M_*D_];
__device__ float g_wq [(size_t)D_*D_];
__device__ float g_wk [(size_t)D_*D_];
__device__ float g_wv [(size_t)D_*D_];
__device__ float g_wo [(size_t)D_*D_];
__device__ float g_w1 [(size_t)D_*HID_];
__device__ float g_w2 [(size_t)HID_*D_];

// ---------------- helpers ----------------------------------------------------
__device__ __forceinline__ void cp_async16(uint32_t s, const float* g) {
    asm volatile("cp.async.cg.shared.global [%0], [%1], 16;\n" :: "r"(s), "l"(g));
}
__device__ __forceinline__ void cp_commit() {
    asm volatile("cp.async.commit_group;\n");
}
__device__ __forceinline__ float rnd_tf32(float f) {
    uint32_t u;
    asm("cvt.rna.tf32.f32 %0, %1;\n" : "=r"(u) : "f"(f));
    return __uint_as_float(u);
}
__device__ __forceinline__ uint32_t f2tf32(float f) {
    uint32_t u;
    asm("cvt.rna.tf32.f32 %0, %1;\n" : "=r"(u) : "f"(f));
    return u;
}
__device__ __forceinline__ void mma_tf32(float c[4],
    uint32_t a0, uint32_t a1, uint32_t a2, uint32_t a3,
    uint32_t b0, uint32_t b1)
{
    asm volatile(
        "mma.sync.aligned.m16n8k8.row.col.f32.tf32.tf32.f32 "
        "{%0,%1,%2,%3}, {%4,%5,%6,%7}, {%8,%9}, {%0,%1,%2,%3};\n"
        : "+f"(c[0]), "+f"(c[1]), "+f"(c[2]), "+f"(c[3])
        : "r"(a0), "r"(a1), "r"(a2), "r"(a3), "r"(b0), "r"(b1));
}

// ---------------- elementwise tf32 rounding ----------------------------------
__global__ __launch_bounds__(256) void round_tf32_kernel(
    const float* __restrict__ in, float* __restrict__ out, int n4)
{
    int i = (blockIdx.x * 256 + threadIdx.x);
    if (i < n4) {
        float4 v = ((const float4*)in)[i];
        v.x = rnd_tf32(v.x); v.y = rnd_tf32(v.y);
        v.z = rnd_tf32(v.z); v.w = rnd_tf32(v.w);
        ((float4*)out)[i] = v;
    }
}

// ---------------- tf32 tensor-core GEMM --------------------------------------
// MODE 0: plain NN (B [K,N]). BN=128. C = A@B + bias (+gelu). Operands
//         pre-rounded -> raw fragment loads.
// MODE 2: AV (batched NN). BN=64. A = fp32 P' (cvt on A-fragments only);
//         C = inv[row]*(A@B); normalized fp32 P -> wb in-place.
// MODE 3: NN like MODE0 but epilogue splits: C = rnd(v), wb = rnd(v - rnd(v)).
// RND: round C to tf32 before store.
template<int BN, int MODE, int ACT, int RND, int STAGES>
__global__ __launch_bounds__(256) void tf32_gemm(
    const float* __restrict__ A, const float* __restrict__ Bm,
    const float* __restrict__ bias, const float* __restrict__ extra,
    float* __restrict__ wb, float* __restrict__ C,
    int M, int N, int K, int lda, int ldb, int ldc)
{
    constexpr int  BM = 128, BK = 16;
    constexpr int  BROWS = BK;
    constexpr int  BCOLS = BN + 4;
    constexpr int  WN = BN / 4;
    constexpr int  NTILE = WN / 8;

    __shared__ float As[STAGES][BM][20];
    __shared__ float Bs[STAGES][BROWS][BCOLS];

    const int tid  = threadIdx.x;
    const int lane = tid & 31;
    const int warp = tid >> 5;
    const int warpRow = (warp & 1) * 64;
    const int warpCol = (warp >> 1) * WN;

    size_t aOff = 0, bOff = 0, cOff = 0, zrow = 0;
    if (MODE == 2) {
        int z = blockIdx.z;
        size_t hb = (size_t)(z >> 4) * ((size_t)S_ * D_) + (size_t)(z & 15) * DH_;
        aOff = (size_t)z * S_ * S_; bOff = hb; cOff = hb;
        zrow = (size_t)z * S_;
    }
    const float* Ag = A + aOff;
    const float* Bg = Bm + bOff;
    float* Cg = C + cOff;

    const int row0 = blockIdx.y * BM;
    const int col0 = blockIdx.x * BN;

    const int ar = tid >> 2;            // 0..63 (rows ar, ar+64)
    const int ac = (tid & 3) << 2;      // 0,4,8,12

    const uint32_t sA = (uint32_t)__cvta_generic_to_shared(&As[0][0][0]);
    const uint32_t sB = (uint32_t)__cvta_generic_to_shared(&Bs[0][0][0]);

    auto issue = [&](int k0, int buf) {
        const float* ap = Ag + (size_t)(row0 + ar) * lda + k0 + ac;
        cp_async16(sA + (uint32_t)(((buf * BM + ar) * 20 + ac) * 4), ap);
        cp_async16(sA + (uint32_t)(((buf * BM + ar + 64) * 20 + ac) * 4),
                   ap + (size_t)64 * lda);
        if (BN == 128) {
            const int br = tid >> 5;
            const int bc = (tid & 31) << 2;
            const float* bp = Bg + (size_t)(k0 + br) * ldb + col0 + bc;
            cp_async16(sB + (uint32_t)(((buf * BROWS + br) * BCOLS + bc) * 4), bp);
            cp_async16(sB + (uint32_t)(((buf * BROWS + br + 8) * BCOLS + bc) * 4),
                       bp + (size_t)8 * ldb);
        } else {  // BN == 64
            const int br = tid >> 4;
            const int bc = (tid & 15) << 2;
            const float* bp = Bg + (size_t)(k0 + br) * ldb + col0 + bc;
            cp_async16(sB + (uint32_t)(((buf * BROWS + br) * BCOLS + bc) * 4), bp);
        }
        cp_commit();
    };

    float invA = 0.f, invB = 0.f;
    float* wbp = nullptr;
    if (MODE == 2) {
        invA = extra[zrow + row0 + ar];
        invB = extra[zrow + row0 + ar + 64];
        wbp = wb + aOff;
    }

    float acc[4][NTILE][4];
#pragma unroll
    for (int i = 0; i < 4; i++)
#pragma unroll
        for (int j = 0; j < NTILE; j++)
#pragma unroll
            for (int r = 0; r < 4; r++) acc[i][j][r] = 0.f;

    const int NITER = K / BK;
    const int NPRE = (STAGES - 1 < NITER) ? STAGES - 1 : NITER;
    for (int p = 0; p < NPRE; p++) issue(p * BK, p);

    for (int it = 0; it < NITER; it++) {
        const int buf = it % STAGES;
        if (it < NITER - 1) {
            asm volatile("cp.async.wait_group %0;\n" :: "n"(STAGES - 2) : "memory");
        } else {
            asm volatile("cp.async.wait_group 0;\n" ::: "memory");
        }
        __syncthreads();
        if (it + STAGES - 1 < NITER)
            issue((it + STAGES - 1) * BK, (it + STAGES - 1) % STAGES);

        if (MODE == 2) {
            const int k0 = it * BK;
            float4 pa = *(const float4*)&As[buf][ar][ac];
            float4 pb = *(const float4*)&As[buf][ar + 64][ac];
            float* w0 = wbp + (size_t)(row0 + ar) * lda + k0 + ac;
            float* w1 = wbp + (size_t)(row0 + ar + 64) * lda + k0 + ac;
            *(float4*)w0 = make_float4(pa.x*invA, pa.y*invA, pa.z*invA, pa.w*invA);
            *(float4*)w1 = make_float4(pb.x*invB, pb.y*invB, pb.z*invB, pb.w*invB);
        }

#pragma unroll
        for (int kk = 0; kk < BK; kk += 8) {
            uint32_t af[4][4];
#pragma unroll
            for (int i = 0; i < 4; i++) {
                const int r = warpRow + i * 16 + (lane >> 2);
                const int c = kk + (lane & 3);
                if (MODE == 2) {
                    af[i][0] = f2tf32(As[buf][r][c]);
                    af[i][1] = f2tf32(As[buf][r + 8][c]);
                    af[i][2] = f2tf32(As[buf][r][c + 4]);
                    af[i][3] = f2tf32(As[buf][r + 8][c + 4]);
                } else {
                    af[i][0] = __float_as_uint(As[buf][r][c]);
                    af[i][1] = __float_as_uint(As[buf][r + 8][c]);
                    af[i][2] = __float_as_uint(As[buf][r][c + 4]);
                    af[i][3] = __float_as_uint(As[buf][r + 8][c + 4]);
                }
            }
            uint32_t bf[NTILE][2];
#pragma unroll
            for (int j = 0; j < NTILE; j++) {
                const int n = warpCol + j * 8 + (lane >> 2);
                bf[j][0] = __float_as_uint(Bs[buf][kk + (lane & 3)][n]);
                bf[j][1] = __float_as_uint(Bs[buf][kk + 4 + (lane & 3)][n]);
            }
#pragma unroll
            for (int i = 0; i < 4; i++)
#pragma unroll
                for (int j = 0; j < NTILE; j++)
                    mma_tf32(acc[i][j], af[i][0], af[i][1], af[i][2], af[i][3],
                             bf[j][0], bf[j][1]);
        }
    }

    // ---------------- epilogue ----------------------------------------------
#pragma unroll
    for (int i = 0; i < 4; i++) {
        const int r = row0 + warpRow + i * 16 + (lane >> 2);
        float invr = 1.f, invr8 = 1.f;
        if (MODE == 2) {
            invr  = extra[zrow + r];
            invr8 = extra[zrow + r + 8];
        }
#pragma unroll
        for (int j = 0; j < NTILE; j++) {
            const int c = col0 + warpCol + j * 8 + 2 * (lane & 3);
            float bb0 = 0.f, bb1 = 0.f;
            if ((MODE == 0 || MODE == 3) && bias) { bb0 = bias[c]; bb1 = bias[c + 1]; }
            float v0 = acc[i][j][0] + bb0;
            float v1 = acc[i][j][1] + bb1;
            float v2 = acc[i][j][2] + bb0;
            float v3 = acc[i][j][3] + bb1;
            if (MODE == 2) { v0 *= invr; v1 *= invr; v2 *= invr8; v3 *= invr8; }
            if (ACT == 1) {
                v0 = 0.5f * v0 * (1.f + erff(v0 * 0.70710678118654752f));
                v1 = 0.5f * v1 * (1.f + erff(v1 * 0.70710678118654752f));
                v2 = 0.5f * v2 * (1.f + erff(v2 * 0.70710678118654752f));
                v3 = 0.5f * v3 * (1.f + erff(v3 * 0.70710678118654752f));
            }
            if (MODE == 3) {
                float h0 = rnd_tf32(v0), h1 = rnd_tf32(v1);
                float h2 = rnd_tf32(v2), h3 = rnd_tf32(v3);
                *(float2*)(Cg + (size_t)r * ldc + c)       = make_float2(h0, h1);
                *(float2*)(Cg + (size_t)(r + 8) * ldc + c) = make_float2(h2, h3);
                *(float2*)(wb + (size_t)r * ldc + c)
                    = make_float2(rnd_tf32(v0 - h0), rnd_tf32(v1 - h1));
                *(float2*)(wb + (size_t)(r + 8) * ldc + c)
                    = make_float2(rnd_tf32(v2 - h2), rnd_tf32(v3 - h3));
            } else {
                if (RND) {
                    v0 = rnd_tf32(v0); v1 = rnd_tf32(v1);
                    v2 = rnd_tf32(v2); v3 = rnd_tf32(v3);
                }
                *(float2*)(Cg + (size_t)r * ldc + c)       = make_float2(v0, v1);
                *(float2*)(Cg + (size_t)(r + 8) * ldc + c) = make_float2(v2, v3);
            }
        }
    }
}

// ---------------- 3xTF32 energy kernel ---------------------------------------
// E = (qh+ql)@(kh+kl)^T ~= qh@kh + qh@kl + ql@kh  (error ~2^-21)
// Writes exp(E/8) fp32 into P; per-row partial sums into psum.
// Dynamic smem: Ah/Al/Bh/Bl, each [2][128][20] floats (80 KB total).
__global__ __launch_bounds__(256) void energy3_kernel(
    const float* __restrict__ qh, const float* __restrict__ ql,
    const float* __restrict__ kh, const float* __restrict__ kl,
    float* __restrict__ psum, float* __restrict__ P)
{
    extern __shared__ float sm[];
    constexpr int PL = 2 * 128 * 20;           // plane size (floats)
    float* Ah = sm;
    float* Al = sm + PL;
    float* Bh = sm + 2 * PL;
    float* Bl = sm + 3 * PL;
    __shared__ float red[128][5];

    const int tid  = threadIdx.x;
    const int lane = tid & 31;
    const int warp = tid >> 5;
    const int warpRow = (warp & 1) * 64;
    const int warpCol = (warp >> 1) * 32;

    const int z = blockIdx.z;
    const size_t hb = (size_t)(z >> 4) * ((size_t)S_ * D_) + (size_t)(z & 15) * DH_;
    const size_t cOff = (size_t)z * S_ * S_;
    const size_t zrow = (size_t)z * S_;

    const int row0 = blockIdx.y * 128;
    const int col0 = blockIdx.x * 128;

    const int ar = tid >> 2;
    const int ac = (tid & 3) << 2;

    const uint32_t sAh = (uint32_t)__cvta_generic_to_shared(Ah);
    const uint32_t sAl = (uint32_t)__cvta_generic_to_shared(Al);
    const uint32_t sBh = (uint32_t)__cvta_generic_to_shared(Bh);
    const uint32_t sBl = (uint32_t)__cvta_generic_to_shared(Bl);

    auto issue = [&](int k0, int buf) {
        const uint32_t so = (uint32_t)(((buf * 128 + ar) * 20 + ac) * 4);
        const uint32_t so2 = (uint32_t)(((buf * 128 + ar + 64) * 20 + ac) * 4);
        const size_t aoff = hb + (size_t)(row0 + ar) * D_ + k0 + ac;
        const size_t boff = hb + (size_t)(col0 + ar) * D_ + k0 + ac;
        cp_async16(sAh + so,  qh + aoff);
        cp_async16(sAh + so2, qh + aoff + (size_t)64 * D_);
        cp_async16(sAl + so,  ql + aoff);
        cp_async16(sAl + so2, ql + aoff + (size_t)64 * D_);
        cp_async16(sBh + so,  kh + boff);
        cp_async16(sBh + so2, kh + boff + (size_t)64 * D_);
        cp_async16(sBl + so,  kl + boff);
        cp_async16(sBl + so2, kl + boff + (size_t)64 * D_);
        cp_commit();
    };

    float acc[4][4][4];
#pragma unroll
    for (int i = 0; i < 4; i++)
#pragma unroll
        for (int j = 0; j < 4; j++)
#pragma unroll
            for (int r = 0; r < 4; r++) acc[i][j][r] = 0.f;

    issue(0, 0);

    const int NITER = DH_ / 16;   // 4
    for (int it = 0; it < NITER; it++) {
        const int buf = it & 1;
        asm volatile("cp.async.wait_group 0;\n" ::: "memory");
        __syncthreads();
        if (it + 1 < NITER) issue((it + 1) * 16, buf ^ 1);

#pragma unroll
        for (int kk = 0; kk < 16; kk += 8) {
            const int cfrag = kk + (lane & 3);
            uint32_t ah[4][4], bh[4][2], bl[4][2];
#pragma unroll
            for (int i = 0; i < 4; i++) {
                const int r = warpRow + i * 16 + (lane >> 2);
                const int base = (buf * 128 + r) * 20 + cfrag;
                ah[i][0] = __float_as_uint(Ah[base]);
                ah[i][1] = __float_as_uint(Ah[base + 8 * 20]);
                ah[i][2] = __float_as_uint(Ah[base + 4]);
                ah[i][3] = __float_as_uint(Ah[base + 8 * 20 + 4]);
            }
#pragma unroll
            for (int j = 0; j < 4; j++) {
                const int n = warpCol + j * 8 + (lane >> 2);
                const int base = (buf * 128 + n) * 20 + cfrag;
                bh[j][0] = __float_as_uint(Bh[base]);
                bh[j][1] = __float_as_uint(Bh[base + 4]);
                bl[j][0] = __float_as_uint(Bl[base]);
                bl[j][1] = __float_as_uint(Bl[base + 4]);
            }
            // hi * hi
#pragma unroll
            for (int i = 0; i < 4; i++)
#pragma unroll
                for (int j = 0; j < 4; j++)
                    mma_tf32(acc[i][j], ah[i][0], ah[i][1], ah[i][2], ah[i][3],
                             bh[j][0], bh[j][1]);
            // hi * lo
#pragma unroll
            for (int i = 0; i < 4; i++)
#pragma unroll
                for (int j = 0; j < 4; j++)
                    mma_tf32(acc[i][j], ah[i][0], ah[i][1], ah[i][2], ah[i][3],
                             bl[j][0], bl[j][1]);
            // lo * hi (reuse ah registers for al)
#pragma unroll
            for (int i = 0; i < 4; i++) {
                const int r = warpRow + i * 16 + (lane >> 2);
                const int base = (buf * 128 + r) * 20 + cfrag;
                ah[i][0] = __float_as_uint(Al[base]);
                ah[i][1] = __float_as_uint(Al[base + 8 * 20]);
                ah[i][2] = __float_as_uint(Al[base + 4]);
                ah[i][3] = __float_as_uint(Al[base + 8 * 20 + 4]);
            }
#pragma unroll
            for (int i = 0; i < 4; i++)
#pragma unroll
                for (int j = 0; j < 4; j++)
                    mma_tf32(acc[i][j], ah[i][0], ah[i][1], ah[i][2], ah[i][3],
                             bh[j][0], bh[j][1]);
        }
    }

    // exp(acc/8) fp32; per-row partial sums; store
#pragma unroll
    for (int i = 0; i < 4; i++)
#pragma unroll
        for (int j = 0; j < 4; j++)
#pragma unroll
            for (int r = 0; r < 4; r++)
                acc[i][j][r] = expf(acc[i][j][r] * 0.125f);

    __syncthreads();
#pragma unroll
    for (int i = 0; i < 4; i++) {
        float sA2 = 0.f, sB2 = 0.f;
#pragma unroll
        for (int j = 0; j < 4; j++) {
            sA2 += acc[i][j][0] + acc[i][j][1];
            sB2 += acc[i][j][2] + acc[i][j][3];
        }
        sA2 += __shfl_xor_sync(0xffffffffu, sA2, 1);
        sA2 += __shfl_xor_sync(0xffffffffu, sA2, 2);
        sB2 += __shfl_xor_sync(0xffffffffu, sB2, 1);
        sB2 += __shfl_xor_sync(0xffffffffu, sB2, 2);
        if ((lane & 3) == 0) {
            red[warpRow + i * 16 + (lane >> 2)][warp >> 1] = sA2;
            red[warpRow + i * 16 + (lane >> 2) + 8][warp >> 1] = sB2;
        }
    }
    __syncthreads();
    if (tid < 128) {
        float s = red[tid][0] + red[tid][1] + red[tid][2] + red[tid][3];
        psum[(zrow + row0 + tid) * 16 + blockIdx.x] = s;
    }

    float* Pg = P + cOff;
#pragma unroll
    for (int i = 0; i < 4; i++) {
        const int r = row0 + warpRow + i * 16 + (lane >> 2);
#pragma unroll
        for (int j = 0; j < 4; j++) {
            const int c = col0 + warpCol + j * 8 + 2 * (lane & 3);
            *(float2*)(Pg + (size_t)r * S_ + c)       = make_float2(acc[i][j][0], acc[i][j][1]);
            *(float2*)(Pg + (size_t)(r + 8) * S_ + c) = make_float2(acc[i][j][2], acc[i][j][3]);
        }
    }
}

// ---------------- row-sum inversion ------------------------------------------
__global__ __launch_bounds__(256) void reduce_inv_kernel(
    const float* __restrict__ psum, float* __restrict__ inv)
{
    const int r = blockIdx.x * 256 + threadIdx.x;
    const float* p = psum + (size_t)r * 16;
    float s = 0.f;
#pragma unroll
    for (int i = 0; i < 16; i++) s += p[i];
    inv[r] = 1.0f / s;
}

// ---------------- fused residual add + LayerNorm over D_ = 1024 -------------
template<int RND>
__global__ __launch_bounds__(256) void add_ln_kernel(
    const float* __restrict__ a, const float* __restrict__ bres,
    const float* __restrict__ gamma, const float* __restrict__ beta,
    float* __restrict__ out)
{
    const size_t row = blockIdx.x;
    const int tid = threadIdx.x;
    const size_t off = row * D_ + tid * 4;

    float4 va = *(const float4*)(a + off);
    float4 vb = *(const float4*)(bres + off);
    float x0 = va.x + vb.x;
    float x1 = va.y + vb.y;
    float x2 = va.z + vb.z;
    float x3 = va.w + vb.w;

    float s  = x0 + x1 + x2 + x3;
    float sq = x0*x0 + x1*x1 + x2*x2 + x3*x3;
#pragma unroll
    for (int o = 16; o; o >>= 1) {
        s  += __shfl_xor_sync(0xffffffffu, s, o);
        sq += __shfl_xor_sync(0xffffffffu, sq, o);
    }
    __shared__ float rs[8];
    __shared__ float rq[8];
    if ((tid & 31) == 0) { rs[tid >> 5] = s; rq[tid >> 5] = sq; }
    __syncthreads();
    s = 0.f; sq = 0.f;
#pragma unroll
    for (int w = 0; w < 8; w++) { s += rs[w]; sq += rq[w]; }

    const float mu  = s * (1.0f / D_);
    const float var = sq * (1.0f / D_) - mu * mu;
    const float inv = rsqrtf(var + 1e-5f);

    float4 g  = *(const float4*)(gamma + tid * 4);
    float4 bt = *(const float4*)(beta + tid * 4);
    float4 o4;
    o4.x = (x0 - mu) * inv * g.x + bt.x;
    o4.y = (x1 - mu) * inv * g.y + bt.y;
    o4.z = (x2 - mu) * inv * g.z + bt.z;
    o4.w = (x3 - mu) * inv * g.w + bt.w;
    if (RND) {
        o4.x = rnd_tf32(o4.x); o4.y = rnd_tf32(o4.y);
        o4.z = rnd_tf32(o4.z); o4.w = rnd_tf32(o4.w);
    }
    *(float4*)(out + off) = o4;
}

// ---------------- launch ----------------------------------------------------
extern "C" void kernel_launch(void* const* d_in, const int* in_sizes, int n_in,
                              void* d_out, int out_size)
{
    const float* x     = (const float*)d_in[0];
    const float* Wq    = (const float*)d_in[1];
    const float* bq    = (const float*)d_in[2];
    const float* Wk    = (const float*)d_in[3];
    const float* bk    = (const float*)d_in[4];
    const float* Wv    = (const float*)d_in[5];
    const float* bv    = (const float*)d_in[6];
    const float* Wo    = (const float*)d_in[7];
    const float* bo    = (const float*)d_in[8];
    const float* W1    = (const float*)d_in[9];
    const float* b1    = (const float*)d_in[10];
    const float* W2    = (const float*)d_in[11];
    const float* b2    = (const float*)d_in[12];
    const float* gamma = (const float*)d_in[13];
    const float* beta  = (const float*)d_in[14];

    float* out  = (float*)d_out;
    float* attn = out + (size_t)B_ * S_ * D_;

    float *q, *k, *qlo, *klo, *v, *ao, *t1, *h, *hid, *psum, *ginv;
    float *xr, *wq, *wk, *wv, *wo, *w1, *w2;
    cudaGetSymbolAddress((void**)&q,    g_q);
    cudaGetSymbolAddress((void**)&k,    g_k);
    cudaGetSymbolAddress((void**)&qlo,  g_qlo);
    cudaGetSymbolAddress((void**)&klo,  g_klo);
    cudaGetSymbolAddress((void**)&v,    g_v);
    cudaGetSymbolAddress((void**)&ao,   g_ao);
    cudaGetSymbolAddress((void**)&t1,   g_t1);
    cudaGetSymbolAddress((void**)&h,    g_h);
    cudaGetSymbolAddress((void**)&hid,  g_hid);
    cudaGetSymbolAddress((void**)&psum, g_psum);
    cudaGetSymbolAddress((void**)&ginv, g_inv);
    cudaGetSymbolAddress((void**)&xr,   g_xr);
    cudaGetSymbolAddress((void**)&wq,   g_wq);
    cudaGetSymbolAddress((void**)&wk,   g_wk);
    cudaGetSymbolAddress((void**)&wv,   g_wv);
    cudaGetSymbolAddress((void**)&wo,   g_wo);
    cudaGetSymbolAddress((void**)&w1,   g_w1);
    cudaGetSymbolAddress((void**)&w2,   g_w2);

    const int ESMEM = 4 * 2 * 128 * 20 * 4;   // 81920 B
    static int smem_set = 0;
    if (!smem_set) {
        cudaFuncSetAttribute(energy3_kernel,
                             cudaFuncAttributeMaxDynamicSharedMemorySize, ESMEM);
        smem_set = 1;
    }

    dim3 blk(256);

    // tf32 pre-rounding of raw inputs
    auto rconv = [&](const float* src, float* dst, size_t n) {
        int n4 = (int)(n / 4);
        round_tf32_kernel<<<(n4 + 255) / 256, blk>>>(src, dst, n4);
    };
    rconv(x,  xr, (size_t)M_ * D_);
    rconv(Wq, wq, (size_t)D_ * D_);
    rconv(Wk, wk, (size_t)D_ * D_);
    rconv(Wv, wv, (size_t)D_ * D_);
    rconv(Wo, wo, (size_t)D_ * D_);
    rconv(W1, w1, (size_t)D_ * HID_);
    rconv(W2, w2, (size_t)HID_ * D_);

    // QKV: q,k split hi/lo (MODE3); v rounded (MODE0, RND)
    tf32_gemm<128,3,0,0,4><<<dim3(D_/128, M_/128), blk>>>(xr, wq, bq, nullptr, qlo, q, M_, D_, D_, D_, D_, D_);
    tf32_gemm<128,3,0,0,4><<<dim3(D_/128, M_/128), blk>>>(xr, wk, bk, nullptr, klo, k, M_, D_, D_, D_, D_, D_);
    tf32_gemm<128,0,0,1,4><<<dim3(D_/128, M_/128), blk>>>(xr, wv, bv, nullptr, nullptr, v, M_, D_, D_, D_, D_, D_);

    // energy (3xTF32) -> fp32 exp(e/8) into attn + row partial sums
    energy3_kernel<<<dim3(S_/128, S_/128, B_*H_), blk, ESMEM>>>(q, qlo, k, klo, psum, attn);
    reduce_inv_kernel<<<NROWS_/256, blk>>>(psum, ginv);

    // AV: ao = inv*(P'@V) (rounded, consumed by Wo); normalizes attn in-place
    tf32_gemm<64,2,0,1,4><<<dim3(1, S_/128, B_*H_), blk>>>(attn, v, nullptr, ginv, attn, ao,
                                                           S_, DH_, S_, S_, D_, D_);

    // output projection + residual + LN
    tf32_gemm<128,0,0,0,4><<<dim3(D_/128, M_/128), blk>>>(ao, wo, bo, nullptr, nullptr, t1, M_, D_, D_, D_, D_, D_);
    add_ln_kernel<1><<<M_, blk>>>(x, t1, gamma, beta, h);

    // MLP
    tf32_gemm<128,0,1,1,4><<<dim3(HID_/128, M_/128), blk>>>(h, w1, b1, nullptr, nullptr, hid, M_, HID_, D_, D_, HID_, HID_);
    tf32_gemm<128,0,0,0,4><<<dim3(D_/128, M_/128), blk>>>(hid, w2, b2, nullptr, nullptr, t1, M_, D_, HID_, HID_, D_, D_);
    add_ln_kernel<0><<<M_, blk>>>(t1, h, gamma, beta, out);
}

// round 11
// speedup vs baseline: 1.1775x; 1.1775x over previous
#include <cuda_runtime.h>
#include <cuda_fp16.h>
#include <math.h>
#include <stdint.h>

#define B_   2
#define S_   2048
#define H_   16
#define DH_  64
#define D_   1024
#define HID_ 4096
#define M_   (B_*S_)        // 4096 tokens
#define NROWS_ (B_*H_*S_)   // 65536 attn rows

// ---------------- scratch (static device globals; no runtime alloc) ----------
__device__ __half g_qh[(size_t)M_*D_];
__device__ __half g_ql[(size_t)M_*D_];
__device__ __half g_kh[(size_t)M_*D_];
__device__ __half g_kl[(size_t)M_*D_];
__device__ float g_v  [(size_t)M_*D_];
__device__ float g_ao [(size_t)M_*D_];
__device__ float g_t1 [(size_t)M_*D_];
__device__ float g_h  [(size_t)M_*D_];
__device__ float g_hid[(size_t)M_*HID_];
__device__ float g_psum[(size_t)NROWS_*16];
__device__ float g_inv [(size_t)NROWS_];
// tf32-rounded copies of raw inputs
__device__ float g_xr [(size_t)M_*D_];
__device__ float g_wq [(size_t)D_*D_];
__device__ float g_wk [(size_t)D_*D_];
__device__ float g_wv [(size_t)D_*D_];
__device__ float g_wo [(size_t)D_*D_];
__device__ float g_w1 [(size_t)D_*HID_];
__device__ float g_w2 [(size_t)HID_*D_];

// ---------------- helpers ----------------------------------------------------
__device__ __forceinline__ void cp_async16(uint32_t s, const void* g) {
    asm volatile("cp.async.cg.shared.global [%0], [%1], 16;\n" :: "r"(s), "l"(g));
}
__device__ __forceinline__ void cp_commit() {
    asm volatile("cp.async.commit_group;\n");
}
__device__ __forceinline__ float rnd_tf32(float f) {
    uint32_t u;
    asm("cvt.rna.tf32.f32 %0, %1;\n" : "=r"(u) : "f"(f));
    return __uint_as_float(u);
}
__device__ __forceinline__ uint32_t f2tf32(float f) {
    uint32_t u;
    asm("cvt.rna.tf32.f32 %0, %1;\n" : "=r"(u) : "f"(f));
    return u;
}
__device__ __forceinline__ void mma_tf32(float c[4],
    uint32_t a0, uint32_t a1, uint32_t a2, uint32_t a3,
    uint32_t b0, uint32_t b1)
{
    asm volatile(
        "mma.sync.aligned.m16n8k8.row.col.f32.tf32.tf32.f32 "
        "{%0,%1,%2,%3}, {%4,%5,%6,%7}, {%8,%9}, {%0,%1,%2,%3};\n"
        : "+f"(c[0]), "+f"(c[1]), "+f"(c[2]), "+f"(c[3])
        : "r"(a0), "r"(a1), "r"(a2), "r"(a3), "r"(b0), "r"(b1));
}
__device__ __forceinline__ void mma_f16(float c[4],
    uint32_t a0, uint32_t a1, uint32_t a2, uint32_t a3,
    uint32_t b0, uint32_t b1)
{
    asm volatile(
        "mma.sync.aligned.m16n8k16.row.col.f32.f16.f16.f32 "
        "{%0,%1,%2,%3}, {%4,%5,%6,%7}, {%8,%9}, {%0,%1,%2,%3};\n"
        : "+f"(c[0]), "+f"(c[1]), "+f"(c[2]), "+f"(c[3])
        : "r"(a0), "r"(a1), "r"(a2), "r"(a3), "r"(b0), "r"(b1));
}

// ---------------- elementwise tf32 rounding ----------------------------------
__global__ __launch_bounds__(256) void round_tf32_kernel(
    const float* __restrict__ in, float* __restrict__ out, int n4)
{
    int i = (blockIdx.x * 256 + threadIdx.x);
    if (i < n4) {
        float4 v = ((const float4*)in)[i];
        v.x = rnd_tf32(v.x); v.y = rnd_tf32(v.y);
        v.z = rnd_tf32(v.z); v.w = rnd_tf32(v.w);
        ((float4*)out)[i] = v;
    }
}

// ---------------- tf32 tensor-core GEMM --------------------------------------
// MODE 0: plain NN (B [K,N]). BN=128. C = A@B + bias (+gelu), pre-rounded
//         operands -> raw fragment loads. RND: round C to tf32.
// MODE 2: AV (batched NN). BN=64. A = fp32 P' (cvt on A-fragments);
//         C = inv[row]*(A@B); normalized fp32 P -> wb in-place.
// MODE 3: NN, epilogue split to fp16 hi (C) and fp16 lo (wb).
template<int BN, int MODE, int ACT, int RND, int STAGES>
__global__ __launch_bounds__(256) void tf32_gemm(
    const float* __restrict__ A, const float* __restrict__ Bm,
    const float* __restrict__ bias, const float* __restrict__ extra,
    float* __restrict__ wb, float* __restrict__ C,
    int M, int N, int K, int lda, int ldb, int ldc)
{
    constexpr int  BM = 128, BK = 16;
    constexpr int  BROWS = BK;
    constexpr int  BCOLS = BN + 4;
    constexpr int  WN = BN / 4;
    constexpr int  NTILE = WN / 8;

    __shared__ float As[STAGES][BM][20];
    __shared__ float Bs[STAGES][BROWS][BCOLS];

    const int tid  = threadIdx.x;
    const int lane = tid & 31;
    const int warp = tid >> 5;
    const int warpRow = (warp & 1) * 64;
    const int warpCol = (warp >> 1) * WN;

    size_t aOff = 0, bOff = 0, cOff = 0, zrow = 0;
    if (MODE == 2) {
        int z = blockIdx.z;
        size_t hb = (size_t)(z >> 4) * ((size_t)S_ * D_) + (size_t)(z & 15) * DH_;
        aOff = (size_t)z * S_ * S_; bOff = hb; cOff = hb;
        zrow = (size_t)z * S_;
    }
    const float* Ag = A + aOff;
    const float* Bg = Bm + bOff;
    float* Cg = C + cOff;

    const int row0 = blockIdx.y * BM;
    const int col0 = blockIdx.x * BN;

    const int ar = tid >> 2;            // 0..63 (rows ar, ar+64)
    const int ac = (tid & 3) << 2;      // 0,4,8,12

    const uint32_t sA = (uint32_t)__cvta_generic_to_shared(&As[0][0][0]);
    const uint32_t sB = (uint32_t)__cvta_generic_to_shared(&Bs[0][0][0]);

    auto issue = [&](int k0, int buf) {
        const float* ap = Ag + (size_t)(row0 + ar) * lda + k0 + ac;
        cp_async16(sA + (uint32_t)(((buf * BM + ar) * 20 + ac) * 4), ap);
        cp_async16(sA + (uint32_t)(((buf * BM + ar + 64) * 20 + ac) * 4),
                   ap + (size_t)64 * lda);
        if (BN == 128) {
            const int br = tid >> 5;
            const int bc = (tid & 31) << 2;
            const float* bp = Bg + (size_t)(k0 + br) * ldb + col0 + bc;
            cp_async16(sB + (uint32_t)(((buf * BROWS + br) * BCOLS + bc) * 4), bp);
            cp_async16(sB + (uint32_t)(((buf * BROWS + br + 8) * BCOLS + bc) * 4),
                       bp + (size_t)8 * ldb);
        } else {  // BN == 64
            const int br = tid >> 4;
            const int bc = (tid & 15) << 2;
            const float* bp = Bg + (size_t)(k0 + br) * ldb + col0 + bc;
            cp_async16(sB + (uint32_t)(((buf * BROWS + br) * BCOLS + bc) * 4), bp);
        }
        cp_commit();
    };

    float invA = 0.f, invB = 0.f;
    float* wbp = nullptr;
    if (MODE == 2) {
        invA = extra[zrow + row0 + ar];
        invB = extra[zrow + row0 + ar + 64];
        wbp = wb + aOff;
    }

    float acc[4][NTILE][4];
#pragma unroll
    for (int i = 0; i < 4; i++)
#pragma unroll
        for (int j = 0; j < NTILE; j++)
#pragma unroll
            for (int r = 0; r < 4; r++) acc[i][j][r] = 0.f;

    const int NITER = K / BK;
    const int NPRE = (STAGES - 1 < NITER) ? STAGES - 1 : NITER;
    for (int p = 0; p < NPRE; p++) issue(p * BK, p);

    for (int it = 0; it < NITER; it++) {
        const int buf = it % STAGES;
        if (it < NITER - 1) {
            asm volatile("cp.async.wait_group %0;\n" :: "n"(STAGES - 2) : "memory");
        } else {
            asm volatile("cp.async.wait_group 0;\n" ::: "memory");
        }
        __syncthreads();
        if (it + STAGES - 1 < NITER)
            issue((it + STAGES - 1) * BK, (it + STAGES - 1) % STAGES);

        if (MODE == 2) {
            const int k0 = it * BK;
            float4 pa = *(const float4*)&As[buf][ar][ac];
            float4 pb = *(const float4*)&As[buf][ar + 64][ac];
            float* w0 = wbp + (size_t)(row0 + ar) * lda + k0 + ac;
            float* w1 = wbp + (size_t)(row0 + ar + 64) * lda + k0 + ac;
            *(float4*)w0 = make_float4(pa.x*invA, pa.y*invA, pa.z*invA, pa.w*invA);
            *(float4*)w1 = make_float4(pb.x*invB, pb.y*invB, pb.z*invB, pb.w*invB);
        }

#pragma unroll
        for (int kk = 0; kk < BK; kk += 8) {
            uint32_t af[4][4];
#pragma unroll
            for (int i = 0; i < 4; i++) {
                const int r = warpRow + i * 16 + (lane >> 2);
                const int c = kk + (lane & 3);
                if (MODE == 2) {
                    af[i][0] = f2tf32(As[buf][r][c]);
                    af[i][1] = f2tf32(As[buf][r + 8][c]);
                    af[i][2] = f2tf32(As[buf][r][c + 4]);
                    af[i][3] = f2tf32(As[buf][r + 8][c + 4]);
                } else {
                    af[i][0] = __float_as_uint(As[buf][r][c]);
                    af[i][1] = __float_as_uint(As[buf][r + 8][c]);
                    af[i][2] = __float_as_uint(As[buf][r][c + 4]);
                    af[i][3] = __float_as_uint(As[buf][r + 8][c + 4]);
                }
            }
            uint32_t bf[NTILE][2];
#pragma unroll
            for (int j = 0; j < NTILE; j++) {
                const int n = warpCol + j * 8 + (lane >> 2);
                bf[j][0] = __float_as_uint(Bs[buf][kk + (lane & 3)][n]);
                bf[j][1] = __float_as_uint(Bs[buf][kk + 4 + (lane & 3)][n]);
            }
#pragma unroll
            for (int i = 0; i < 4; i++)
#pragma unroll
                for (int j = 0; j < NTILE; j++)
                    mma_tf32(acc[i][j], af[i][0], af[i][1], af[i][2], af[i][3],
                             bf[j][0], bf[j][1]);
        }
    }

    // ---------------- epilogue ----------------------------------------------
    __half* Ch = reinterpret_cast<__half*>(C);
    __half* Cl = reinterpret_cast<__half*>(wb);

#pragma unroll
    for (int i = 0; i < 4; i++) {
        const int r = row0 + warpRow + i * 16 + (lane >> 2);
        float invr = 1.f, invr8 = 1.f;
        if (MODE == 2) {
            invr  = extra[zrow + r];
            invr8 = extra[zrow + r + 8];
        }
#pragma unroll
        for (int j = 0; j < NTILE; j++) {
            const int c = col0 + warpCol + j * 8 + 2 * (lane & 3);
            float bb0 = 0.f, bb1 = 0.f;
            if ((MODE == 0 || MODE == 3) && bias) { bb0 = bias[c]; bb1 = bias[c + 1]; }
            float v0 = acc[i][j][0] + bb0;
            float v1 = acc[i][j][1] + bb1;
            float v2 = acc[i][j][2] + bb0;
            float v3 = acc[i][j][3] + bb1;
            if (MODE == 2) { v0 *= invr; v1 *= invr; v2 *= invr8; v3 *= invr8; }
            if (ACT == 1) {
                v0 = 0.5f * v0 * (1.f + erff(v0 * 0.70710678118654752f));
                v1 = 0.5f * v1 * (1.f + erff(v1 * 0.70710678118654752f));
                v2 = 0.5f * v2 * (1.f + erff(v2 * 0.70710678118654752f));
                v3 = 0.5f * v3 * (1.f + erff(v3 * 0.70710678118654752f));
            }
            if (MODE == 3) {
                __half2 h01, h23, l01, l23;
                h01.x = __float2half_rn(v0);
                h01.y = __float2half_rn(v1);
                h23.x = __float2half_rn(v2);
                h23.y = __float2half_rn(v3);
                l01.x = __float2half_rn(v0 - __half2float(h01.x));
                l01.y = __float2half_rn(v1 - __half2float(h01.y));
                l23.x = __float2half_rn(v2 - __half2float(h23.x));
                l23.y = __float2half_rn(v3 - __half2float(h23.y));
                *(__half2*)(Ch + (size_t)r * ldc + c)       = h01;
                *(__half2*)(Ch + (size_t)(r + 8) * ldc + c) = h23;
                *(__half2*)(Cl + (size_t)r * ldc + c)       = l01;
                *(__half2*)(Cl + (size_t)(r + 8) * ldc + c) = l23;
            } else {
                if (RND) {
                    v0 = rnd_tf32(v0); v1 = rnd_tf32(v1);
                    v2 = rnd_tf32(v2); v3 = rnd_tf32(v3);
                }
                *(float2*)(Cg + (size_t)r * ldc + c)       = make_float2(v0, v1);
                *(float2*)(Cg + (size_t)(r + 8) * ldc + c) = make_float2(v2, v3);
            }
        }
    }
}

// ---------------- split-fp16 energy kernel -----------------------------------
// E = (qh+ql)@(kh+kl)^T ~= qh@kh + qh@kl + ql@kh  (residual ~2^-22)
// K=64 fits entirely in smem: single load, no pipeline.
// Planes (uint32 words = half2 k-pairs): row stride 36 words (conflict-free).
// Dynamic smem: 4 planes x 128 rows x 36 words x 4B = 73728 B.
__global__ __launch_bounds__(256) void energy_f16_kernel(
    const __half* __restrict__ qh, const __half* __restrict__ ql,
    const __half* __restrict__ kh, const __half* __restrict__ kl,
    float* __restrict__ psum, float* __restrict__ P)
{
    extern __shared__ uint32_t sm[];
    constexpr int PLW = 128 * 36;                 // words per plane
    uint32_t* Ahw = sm;
    uint32_t* Alw = sm + PLW;
    uint32_t* Bhw = sm + 2 * PLW;
    uint32_t* Blw = sm + 3 * PLW;

    const int tid  = threadIdx.x;
    const int lane = tid & 31;
    const int warp = tid >> 5;
    const int warpRow = (warp & 1) * 64;
    const int warpCol = (warp >> 1) * 32;

    const int z = blockIdx.z;
    const size_t hb = (size_t)(z >> 4) * ((size_t)S_ * D_) + (size_t)(z & 15) * DH_;
    const size_t cOff = (size_t)z * S_ * S_;
    const size_t zrow = (size_t)z * S_;

    const int row0 = blockIdx.y * 128;
    const int col0 = blockIdx.x * 128;

    const uint32_t sBase = (uint32_t)__cvta_generic_to_shared(sm);

    // load all four planes (4 x 16B chunks per thread per plane)
#pragma unroll
    for (int c = 0; c < 4; c++) {
        const int id  = tid + c * 256;     // 0..1023
        const int row = id >> 3;           // 0..127
        const int cw  = id & 7;            // 16B chunk within 128B row
        const uint32_t dst = (uint32_t)((row * 36 + cw * 4) * 4);
        const size_t aoff = hb + (size_t)(row0 + row) * D_ + cw * 8;
        const size_t boff = hb + (size_t)(col0 + row) * D_ + cw * 8;
        cp_async16(sBase + 0 * PLW * 4 + dst, qh + aoff);
        cp_async16(sBase + 1 * PLW * 4 + dst, ql + aoff);
        cp_async16(sBase + 2 * PLW * 4 + dst, kh + boff);
        cp_async16(sBase + 3 * PLW * 4 + dst, kl + boff);
    }
    cp_commit();
    asm volatile("cp.async.wait_group 0;\n" ::: "memory");
    __syncthreads();

    float acc[4][4][4];
#pragma unroll
    for (int i = 0; i < 4; i++)
#pragma unroll
        for (int j = 0; j < 4; j++)
#pragma unroll
            for (int r = 0; r < 4; r++) acc[i][j][r] = 0.f;

#pragma unroll
    for (int c = 0; c < 4; c++) {         // 4 k16 chunks
        const int cw = c * 8 + (lane & 3);
        uint32_t ah[4][4], al[4][4], bh[4][2], bl[4][2];
#pragma unroll
        for (int i = 0; i < 4; i++) {
            const int base = (warpRow + i * 16 + (lane >> 2)) * 36 + cw;
            ah[i][0] = Ahw[base];
            ah[i][1] = Ahw[base + 8 * 36];
            ah[i][2] = Ahw[base + 4];
            ah[i][3] = Ahw[base + 8 * 36 + 4];
            al[i][0] = Alw[base];
            al[i][1] = Alw[base + 8 * 36];
            al[i][2] = Alw[base + 4];
            al[i][3] = Alw[base + 8 * 36 + 4];
        }
#pragma unroll
        for (int j = 0; j < 4; j++) {
            const int bbase = (warpCol + j * 8 + (lane >> 2)) * 36 + cw;
            bh[j][0] = Bhw[bbase];
            bh[j][1] = Bhw[bbase + 4];
            bl[j][0] = Blw[bbase];
            bl[j][1] = Blw[bbase + 4];
        }
#pragma unroll
        for (int i = 0; i < 4; i++)
#pragma unroll
            for (int j = 0; j < 4; j++) {
                mma_f16(acc[i][j], ah[i][0], ah[i][1], ah[i][2], ah[i][3],
                        bh[j][0], bh[j][1]);
                mma_f16(acc[i][j], ah[i][0], ah[i][1], ah[i][2], ah[i][3],
                        bl[j][0], bl[j][1]);
                mma_f16(acc[i][j], al[i][0], al[i][1], al[i][2], al[i][3],
                        bh[j][0], bh[j][1]);
            }
    }

    // exp(acc/8) fp32; per-row partial sums; store
#pragma unroll
    for (int i = 0; i < 4; i++)
#pragma unroll
        for (int j = 0; j < 4; j++)
#pragma unroll
            for (int r = 0; r < 4; r++)
                acc[i][j][r] = expf(acc[i][j][r] * 0.125f);

    __syncthreads();                       // planes done; alias red onto smem
    float (*red)[5] = (float(*)[5])sm;
#pragma unroll
    for (int i = 0; i < 4; i++) {
        float sA2 = 0.f, sB2 = 0.f;
#pragma unroll
        for (int j = 0; j < 4; j++) {
            sA2 += acc[i][j][0] + acc[i][j][1];
            sB2 += acc[i][j][2] + acc[i][j][3];
        }
        sA2 += __shfl_xor_sync(0xffffffffu, sA2, 1);
        sA2 += __shfl_xor_sync(0xffffffffu, sA2, 2);
        sB2 += __shfl_xor_sync(0xffffffffu, sB2, 1);
        sB2 += __shfl_xor_sync(0xffffffffu, sB2, 2);
        if ((lane & 3) == 0) {
            red[warpRow + i * 16 + (lane >> 2)][warp >> 1] = sA2;
            red[warpRow + i * 16 + (lane >> 2) + 8][warp >> 1] = sB2;
        }
    }
    __syncthreads();
    if (tid < 128) {
        float s = red[tid][0] + red[tid][1] + red[tid][2] + red[tid][3];
        psum[(zrow + row0 + tid) * 16 + blockIdx.x] = s;
    }

    float* Pg = P + cOff;
#pragma unroll
    for (int i = 0; i < 4; i++) {
        const int r = row0 + warpRow + i * 16 + (lane >> 2);
#pragma unroll
        for (int j = 0; j < 4; j++) {
            const int c = col0 + warpCol + j * 8 + 2 * (lane & 3);
            *(float2*)(Pg + (size_t)r * S_ + c)       = make_float2(acc[i][j][0], acc[i][j][1]);
            *(float2*)(Pg + (size_t)(r + 8) * S_ + c) = make_float2(acc[i][j][2], acc[i][j][3]);
        }
    }
}

// ---------------- row-sum inversion ------------------------------------------
__global__ __launch_bounds__(256) void reduce_inv_kernel(
    const float* __restrict__ psum, float* __restrict__ inv)
{
    const int r = blockIdx.x * 256 + threadIdx.x;
    const float* p = psum + (size_t)r * 16;
    float s = 0.f;
#pragma unroll
    for (int i = 0; i < 16; i++) s += p[i];
    inv[r] = 1.0f / s;
}

// ---------------- fused residual add + LayerNorm over D_ = 1024 -------------
template<int RND>
__global__ __launch_bounds__(256) void add_ln_kernel(
    const float* __restrict__ a, const float* __restrict__ bres,
    const float* __restrict__ gamma, const float* __restrict__ beta,
    float* __restrict__ out)
{
    const size_t row = blockIdx.x;
    const int tid = threadIdx.x;
    const size_t off = row * D_ + tid * 4;

    float4 va = *(const float4*)(a + off);
    float4 vb = *(const float4*)(bres + off);
    float x0 = va.x + vb.x;
    float x1 = va.y + vb.y;
    float x2 = va.z + vb.z;
    float x3 = va.w + vb.w;

    float s  = x0 + x1 + x2 + x3;
    float sq = x0*x0 + x1*x1 + x2*x2 + x3*x3;
#pragma unroll
    for (int o = 16; o; o >>= 1) {
        s  += __shfl_xor_sync(0xffffffffu, s, o);
        sq += __shfl_xor_sync(0xffffffffu, sq, o);
    }
    __shared__ float rs[8];
    __shared__ float rq[8];
    if ((tid & 31) == 0) { rs[tid >> 5] = s; rq[tid >> 5] = sq; }
    __syncthreads();
    s = 0.f; sq = 0.f;
#pragma unroll
    for (int w = 0; w < 8; w++) { s += rs[w]; sq += rq[w]; }

    const float mu  = s * (1.0f / D_);
    const float var = sq * (1.0f / D_) - mu * mu;
    const float inv = rsqrtf(var + 1e-5f);

    float4 g  = *(const float4*)(gamma + tid * 4);
    float4 bt = *(const float4*)(beta + tid * 4);
    float4 o4;
    o4.x = (x0 - mu) * inv * g.x + bt.x;
    o4.y = (x1 - mu) * inv * g.y + bt.y;
    o4.z = (x2 - mu) * inv * g.z + bt.z;
    o4.w = (x3 - mu) * inv * g.w + bt.w;
    if (RND) {
        o4.x = rnd_tf32(o4.x); o4.y = rnd_tf32(o4.y);
        o4.z = rnd_tf32(o4.z); o4.w = rnd_tf32(o4.w);
    }
    *(float4*)(out + off) = o4;
}

// ---------------- launch ----------------------------------------------------
extern "C" void kernel_launch(void* const* d_in, const int* in_sizes, int n_in,
                              void* d_out, int out_size)
{
    const float* x     = (const float*)d_in[0];
    const float* Wq    = (const float*)d_in[1];
    const float* bq    = (const float*)d_in[2];
    const float* Wk    = (const float*)d_in[3];
    const float* bk    = (const float*)d_in[4];
    const float* Wv    = (const float*)d_in[5];
    const float* bv    = (const float*)d_in[6];
    const float* Wo    = (const float*)d_in[7];
    const float* bo    = (const float*)d_in[8];
    const float* W1    = (const float*)d_in[9];
    const float* b1    = (const float*)d_in[10];
    const float* W2    = (const float*)d_in[11];
    const float* b2    = (const float*)d_in[12];
    const float* gamma = (const float*)d_in[13];
    const float* beta  = (const float*)d_in[14];

    float* out  = (float*)d_out;
    float* attn = out + (size_t)B_ * S_ * D_;

    __half *qh, *ql, *kh, *kl;
    float *v, *ao, *t1, *h, *hid, *psum, *ginv;
    float *xr, *wq, *wk, *wv, *wo, *w1, *w2;
    cudaGetSymbolAddress((void**)&qh,   g_qh);
    cudaGetSymbolAddress((void**)&ql,   g_ql);
    cudaGetSymbolAddress((void**)&kh,   g_kh);
    cudaGetSymbolAddress((void**)&kl,   g_kl);
    cudaGetSymbolAddress((void**)&v,    g_v);
    cudaGetSymbolAddress((void**)&ao,   g_ao);
    cudaGetSymbolAddress((void**)&t1,   g_t1);
    cudaGetSymbolAddress((void**)&h,    g_h);
    cudaGetSymbolAddress((void**)&hid,  g_hid);
    cudaGetSymbolAddress((void**)&psum, g_psum);
    cudaGetSymbolAddress((void**)&ginv, g_inv);
    cudaGetSymbolAddress((void**)&xr,   g_xr);
    cudaGetSymbolAddress((void**)&wq,   g_wq);
    cudaGetSymbolAddress((void**)&wk,   g_wk);
    cudaGetSymbolAddress((void**)&wv,   g_wv);
    cudaGetSymbolAddress((void**)&wo,   g_wo);
    cudaGetSymbolAddress((void**)&w1,   g_w1);
    cudaGetSymbolAddress((void**)&w2,   g_w2);

    const int ESMEM = 4 * 128 * 36 * 4;   // 73728 B
    static int smem_set = 0;
    if (!smem_set) {
        cudaFuncSetAttribute(energy_f16_kernel,
                             cudaFuncAttributeMaxDynamicSharedMemorySize, ESMEM);
        smem_set = 1;
    }

    dim3 blk(256);

    // tf32 pre-rounding of raw inputs
    auto rconv = [&](const float* src, float* dst, size_t n) {
        int n4 = (int)(n / 4);
        round_tf32_kernel<<<(n4 + 255) / 256, blk>>>(src, dst, n4);
    };
    rconv(x,  xr, (size_t)M_ * D_);
    rconv(Wq, wq, (size_t)D_ * D_);
    rconv(Wk, wk, (size_t)D_ * D_);
    rconv(Wv, wv, (size_t)D_ * D_);
    rconv(Wo, wo, (size_t)D_ * D_);
    rconv(W1, w1, (size_t)D_ * HID_);
    rconv(W2, w2, (size_t)HID_ * D_);

    // QKV: q,k -> split fp16 hi/lo planes (MODE3); v tf32-rounded fp32
    tf32_gemm<128,3,0,0,4><<<dim3(D_/128, M_/128), blk>>>(xr, wq, bq, nullptr,
        (float*)ql, (float*)qh, M_, D_, D_, D_, D_, D_);
    tf32_gemm<128,3,0,0,4><<<dim3(D_/128, M_/128), blk>>>(xr, wk, bk, nullptr,
        (float*)kl, (float*)kh, M_, D_, D_, D_, D_, D_);
    tf32_gemm<128,0,0,1,4><<<dim3(D_/128, M_/128), blk>>>(xr, wv, bv, nullptr,
        nullptr, v, M_, D_, D_, D_, D_, D_);

    // energy (split-fp16, 3 MMA terms) -> fp32 exp(e/8) + row partial sums
    energy_f16_kernel<<<dim3(S_/128, S_/128, B_*H_), blk, ESMEM>>>(qh, ql, kh, kl, psum, attn);
    reduce_inv_kernel<<<NROWS_/256, blk>>>(psum, ginv);

    // AV: ao = inv*(P'@V) (rounded, consumed by Wo); normalizes attn in-place
    tf32_gemm<64,2,0,1,4><<<dim3(1, S_/128, B_*H_), blk>>>(attn, v, nullptr, ginv,
        attn, ao, S_, DH_, S_, S_, D_, D_);

    // output projection + residual + LN
    tf32_gemm<128,0,0,0,4><<<dim3(D_/128, M_/128), blk>>>(ao, wo, bo, nullptr,
        nullptr, t1, M_, D_, D_, D_, D_, D_);
    add_ln_kernel<1><<<M_, blk>>>(x, t1, gamma, beta, h);

    // MLP
    tf32_gemm<128,0,1,1,4><<<dim3(HID_/128, M_/128), blk>>>(h, w1, b1, nullptr,
        nullptr, hid, M_, HID_, D_, D_, HID_, HID_);
    tf32_gemm<128,0,0,0,4><<<dim3(D_/128, M_/128), blk>>>(hid, w2, b2, nullptr,
        nullptr, t1, M_, D_, HID_, HID_, D_, D_);
    add_ln_kernel<0><<<M_, blk>>>(t1, h, gamma, beta, out);
}

// round 17
// speedup vs baseline: 1.7836x; 1.5147x over previous
#include <cuda_runtime.h>
#include <math.h>
#include <stdint.h>

#define B_   2
#define S_   2048
#define H_   16
#define DH_  64
#define D_   1024
#define HID_ 4096
#define M_   (B_*S_)   // 4096 tokens
#define NROWS_ (B_*H_*S_)   // 65536 attn rows

// ---------------- scratch (static device globals; no runtime alloc) ----------
__device__ float g_q  [(size_t)M_*D_];
__device__ float g_k  [(size_t)M_*D_];
__device__ float g_v  [(size_t)M_*D_];
__device__ float g_ao [(size_t)M_*D_];
__device__ float g_t1 [(size_t)M_*D_];
__device__ float g_h  [(size_t)M_*D_];
__device__ float g_hid[(size_t)M_*HID_];
__device__ float g_psum[(size_t)NROWS_*16];   // per-row partial exp sums (16 col tiles)
__device__ float g_inv [(size_t)NROWS_];      // per-row 1/sum
// pre-rounded operands for the fast (non-attn-path) GEMMs
__device__ float g_xr [(size_t)M_*D_];
__device__ float g_wv [(size_t)D_*D_];
__device__ float g_wo [(size_t)D_*D_];
__device__ float g_w1 [(size_t)D_*HID_];
__device__ float g_w2 [(size_t)HID_*D_];
__device__ float g_aor[(size_t)M_*D_];
__device__ float g_hr [(size_t)M_*D_];

// ---------------- helpers (R3-exact) -----------------------------------------
__device__ __forceinline__ void cp_async16(uint32_t s, const float* g) {
    asm volatile("cp.async.cg.shared.global [%0], [%1], 16;\n" :: "r"(s), "l"(g));
}
__device__ __forceinline__ void cp_commit() {
    asm volatile("cp.async.commit_group;\n");
}
__device__ __forceinline__ uint32_t f2tf32(float f) {
    uint32_t u;
    asm("cvt.rna.tf32.f32 %0, %1;\n" : "=r"(u) : "f"(f));
    return u;
}
__device__ __forceinline__ float rnd_tf32(float f) {
    uint32_t u;
    asm("cvt.rna.tf32.f32 %0, %1;\n" : "=r"(u) : "f"(f));
    return __uint_as_float(u);
}
__device__ __forceinline__ void mma_tf32(float c[4],
    uint32_t a0, uint32_t a1, uint32_t a2, uint32_t a3,
    uint32_t b0, uint32_t b1)
{
    asm volatile(
        "mma.sync.aligned.m16n8k8.row.col.f32.tf32.tf32.f32 "
        "{%0,%1,%2,%3}, {%4,%5,%6,%7}, {%8,%9}, {%0,%1,%2,%3};\n"
        : "+f"(c[0]), "+f"(c[1]), "+f"(c[2]), "+f"(c[3])
        : "r"(a0), "r"(a1), "r"(a2), "r"(a3), "r"(b0), "r"(b1));
}

// ---------------- R3-EXACT tf32 tensor-core GEMM ------------------------------
// MODE 0: plain NN (B global [K,N] row-major). BN=128. C = A@B + bias (+gelu)
// MODE 1: energy (batched NT, B global [N,K]). BN=128.
//         C = exp((A@B^T)/8); per-row partial sums -> wb (psum layout).
// MODE 2: AV (batched NN). BN=64. C = inv[row] * (A@B); also writes
//         normalized A (=P) back to wb in-place while streaming tiles.
// BM=128, BK=16, 3-stage cp.async, 256 threads, 8 warps, warp tile 64 x BN/4.
template<int BN, int MODE, int ACT>
__global__ __launch_bounds__(256) void tf32_gemm(
    const float* __restrict__ A, const float* __restrict__ Bm,
    const float* __restrict__ bias, const float* __restrict__ extra,
    float* __restrict__ wb, float* __restrict__ C,
    int M, int N, int K, int lda, int ldb, int ldc)
{
    constexpr int  BM = 128, BK = 16;
    constexpr bool NT = (MODE == 1);
    constexpr int  BROWS = NT ? BN : BK;
    constexpr int  BCOLS = NT ? 20 : BN + 4;
    constexpr int  WN = BN / 4;
    constexpr int  NTILE = WN / 8;

    __shared__ float As[3][BM][20];
    __shared__ float Bs[3][BROWS][BCOLS];
    __shared__ float red[(MODE == 1) ? 128 : 1][5];

    const int tid  = threadIdx.x;
    const int lane = tid & 31;
    const int warp = tid >> 5;
    const int warpRow = (warp & 1) * 64;
    const int warpCol = (warp >> 1) * WN;

    // batch offsets
    size_t aOff = 0, bOff = 0, cOff = 0, zrow = 0;
    if (MODE == 1) {
        int z = blockIdx.z;
        size_t hb = (size_t)(z >> 4) * ((size_t)S_ * D_) + (size_t)(z & 15) * DH_;
        aOff = hb; bOff = hb; cOff = (size_t)z * S_ * S_;
        zrow = (size_t)z * S_;
    } else if (MODE == 2) {
        int z = blockIdx.z;
        size_t hb = (size_t)(z >> 4) * ((size_t)S_ * D_) + (size_t)(z & 15) * DH_;
        aOff = (size_t)z * S_ * S_; bOff = hb; cOff = hb;
        zrow = (size_t)z * S_;
    }
    const float* Ag = A + aOff;
    const float* Bg = Bm + bOff;
    float* Cg = C + cOff;

    const int row0 = blockIdx.y * BM;
    const int col0 = blockIdx.x * BN;

    const int ar = tid >> 2;            // 0..63 (rows ar, ar+64)
    const int ac = (tid & 3) << 2;      // 0,4,8,12

    const uint32_t sA = (uint32_t)__cvta_generic_to_shared(&As[0][0][0]);
    const uint32_t sB = (uint32_t)__cvta_generic_to_shared(&Bs[0][0][0]);

    auto issue = [&](int k0, int buf) {
        const float* ap = Ag + (size_t)(row0 + ar) * lda + k0 + ac;
        cp_async16(sA + (uint32_t)(((buf * BM + ar) * 20 + ac) * 4), ap);
        cp_async16(sA + (uint32_t)(((buf * BM + ar + 64) * 20 + ac) * 4),
                   ap + (size_t)64 * lda);
        if (NT) {
            const float* bp = Bg + (size_t)(col0 + ar) * ldb + k0 + ac;
            cp_async16(sB + (uint32_t)(((buf * BROWS + ar) * BCOLS + ac) * 4), bp);
            cp_async16(sB + (uint32_t)(((buf * BROWS + ar + 64) * BCOLS + ac) * 4),
                       bp + (size_t)64 * ldb);
        } else if (BN == 128) {
            const int br = tid >> 5;
            const int bc = (tid & 31) << 2;
            const float* bp = Bg + (size_t)(k0 + br) * ldb + col0 + bc;
            cp_async16(sB + (uint32_t)(((buf * BROWS + br) * BCOLS + bc) * 4), bp);
            cp_async16(sB + (uint32_t)(((buf * BROWS + br + 8) * BCOLS + bc) * 4),
                       bp + (size_t)8 * ldb);
        } else {  // BN == 64
            const int br = tid >> 4;
            const int bc = (tid & 15) << 2;
            const float* bp = Bg + (size_t)(k0 + br) * ldb + col0 + bc;
            cp_async16(sB + (uint32_t)(((buf * BROWS + br) * BCOLS + bc) * 4), bp);
        }
        cp_commit();
    };

    // MODE 2: per-loader-row inverse sums (for normalized write-back of P)
    float invA = 0.f, invB = 0.f;
    float* wbp = nullptr;
    if (MODE == 2) {
        invA = extra[zrow + row0 + ar];
        invB = extra[zrow + row0 + ar + 64];
        wbp = wb + aOff;
    }

    float acc[4][NTILE][4];
#pragma unroll
    for (int i = 0; i < 4; i++)
#pragma unroll
        for (int j = 0; j < NTILE; j++)
#pragma unroll
            for (int r = 0; r < 4; r++) acc[i][j][r] = 0.f;

    const int NITER = K / BK;
    issue(0, 0);
    if (NITER > 1) issue(BK, 1);

    for (int it = 0; it < NITER; it++) {
        const int buf = it % 3;
        if (it < NITER - 1) {
            asm volatile("cp.async.wait_group 1;\n" ::: "memory");
        } else {
            asm volatile("cp.async.wait_group 0;\n" ::: "memory");
        }
        __syncthreads();
        if (it + 2 < NITER) issue((it + 2) * BK, (it + 2) % 3);

        if (MODE == 2) {
            // write normalized P back to the attn output while data is hot
            const int k0 = it * BK;
            float4 pa = *(const float4*)&As[buf][ar][ac];
            float4 pb = *(const float4*)&As[buf][ar + 64][ac];
            float* w0 = wbp + (size_t)(row0 + ar) * lda + k0 + ac;
            float* w1 = wbp + (size_t)(row0 + ar + 64) * lda + k0 + ac;
            *(float4*)w0 = make_float4(pa.x*invA, pa.y*invA, pa.z*invA, pa.w*invA);
            *(float4*)w1 = make_float4(pb.x*invB, pb.y*invB, pb.z*invB, pb.w*invB);
        }

#pragma unroll
        for (int kk = 0; kk < BK; kk += 8) {
            uint32_t af[4][4];
#pragma unroll
            for (int i = 0; i < 4; i++) {
                const int r = warpRow + i * 16 + (lane >> 2);
                const int c = kk + (lane & 3);
                af[i][0] = f2tf32(As[buf][r][c]);
                af[i][1] = f2tf32(As[buf][r + 8][c]);
                af[i][2] = f2tf32(As[buf][r][c + 4]);
                af[i][3] = f2tf32(As[buf][r + 8][c + 4]);
            }
            uint32_t bf[NTILE][2];
#pragma unroll
            for (int j = 0; j < NTILE; j++) {
                const int n = warpCol + j * 8 + (lane >> 2);
                if (NT) {
                    bf[j][0] = f2tf32(Bs[buf][n][kk + (lane & 3)]);
                    bf[j][1] = f2tf32(Bs[buf][n][kk + 4 + (lane & 3)]);
                } else {
                    bf[j][0] = f2tf32(Bs[buf][kk + (lane & 3)][n]);
                    bf[j][1] = f2tf32(Bs[buf][kk + 4 + (lane & 3)][n]);
                }
            }
#pragma unroll
            for (int i = 0; i < 4; i++)
#pragma unroll
                for (int j = 0; j < NTILE; j++)
                    mma_tf32(acc[i][j], af[i][0], af[i][1], af[i][2], af[i][3],
                             bf[j][0], bf[j][1]);
        }
    }

    // ---------------- epilogues ---------------------------------------------
    if (MODE == 1) {
        // exp(acc/8), per-row partial sums (deterministic), store exp values
#pragma unroll
        for (int i = 0; i < 4; i++)
#pragma unroll
            for (int j = 0; j < NTILE; j++)
#pragma unroll
                for (int r = 0; r < 4; r++)
                    acc[i][j][r] = expf(acc[i][j][r] * 0.125f);

        __syncthreads();   // red[] reuse barrier (also after mainloop)
#pragma unroll
        for (int i = 0; i < 4; i++) {
            float sA2 = 0.f, sB2 = 0.f;
#pragma unroll
            for (int j = 0; j < NTILE; j++) {
                sA2 += acc[i][j][0] + acc[i][j][1];
                sB2 += acc[i][j][2] + acc[i][j][3];
            }
            sA2 += __shfl_xor_sync(0xffffffffu, sA2, 1);
            sA2 += __shfl_xor_sync(0xffffffffu, sA2, 2);
            sB2 += __shfl_xor_sync(0xffffffffu, sB2, 1);
            sB2 += __shfl_xor_sync(0xffffffffu, sB2, 2);
            if ((lane & 3) == 0) {
                red[warpRow + i * 16 + (lane >> 2)][warp >> 1] = sA2;
                red[warpRow + i * 16 + (lane >> 2) + 8][warp >> 1] = sB2;
            }
        }
        __syncthreads();
        if (tid < 128) {
            float s = red[tid][0] + red[tid][1] + red[tid][2] + red[tid][3];
            wb[(zrow + row0 + tid) * 16 + blockIdx.x] = s;
        }
    }

#pragma unroll
    for (int i = 0; i < 4; i++) {
        const int r = row0 + warpRow + i * 16 + (lane >> 2);
        float invr = 1.f, invr8 = 1.f;
        if (MODE == 2) {
            invr  = extra[zrow + r];
            invr8 = extra[zrow + r + 8];
        }
#pragma unroll
        for (int j = 0; j < NTILE; j++) {
            const int c = col0 + warpCol + j * 8 + 2 * (lane & 3);
            float bb0 = 0.f, bb1 = 0.f;
            if (MODE == 0 && bias) { bb0 = bias[c]; bb1 = bias[c + 1]; }
            float v0 = acc[i][j][0] + bb0;
            float v1 = acc[i][j][1] + bb1;
            float v2 = acc[i][j][2] + bb0;
            float v3 = acc[i][j][3] + bb1;
            if (MODE == 2) { v0 *= invr; v1 *= invr; v2 *= invr8; v3 *= invr8; }
            if (ACT == 1) {
                v0 = 0.5f * v0 * (1.f + erff(v0 * 0.70710678118654752f));
                v1 = 0.5f * v1 * (1.f + erff(v1 * 0.70710678118654752f));
                v2 = 0.5f * v2 * (1.f + erff(v2 * 0.70710678118654752f));
                v3 = 0.5f * v3 * (1.f + erff(v3 * 0.70710678118654752f));
            }
            *(float2*)(Cg + (size_t)r * ldc + c)       = make_float2(v0, v1);
            *(float2*)(Cg + (size_t)(r + 8) * ldc + c) = make_float2(v2, v3);
        }
    }
}

// ---------------- fast NN GEMM (non-attn path only) ---------------------------
// Pre-rounded operands, raw fragment loads (no cvt), 4-stage pipeline.
// C = A@B + bias (+gelu). RND rounds C to tf32 for downstream raw-load GEMMs.
template<int ACT, int RND>
__global__ __launch_bounds__(256) void fgemm(
    const float* __restrict__ A, const float* __restrict__ Bm,
    const float* __restrict__ bias, float* __restrict__ C,
    int M, int N, int K, int lda, int ldb, int ldc)
{
    constexpr int BM = 128, BN = 128, BK = 16, STAGES = 4;

    __shared__ float As[STAGES][BM][20];
    __shared__ float Bs[STAGES][BK][BN + 4];

    const int tid  = threadIdx.x;
    const int lane = tid & 31;
    const int warp = tid >> 5;
    const int warpRow = (warp & 1) * 64;
    const int warpCol = (warp >> 1) * 32;

    const int row0 = blockIdx.y * BM;
    const int col0 = blockIdx.x * BN;

    const int ar = tid >> 2;
    const int ac = (tid & 3) << 2;

    const uint32_t sA = (uint32_t)__cvta_generic_to_shared(&As[0][0][0]);
    const uint32_t sB = (uint32_t)__cvta_generic_to_shared(&Bs[0][0][0]);

    auto issue = [&](int k0, int buf) {
        const float* ap = A + (size_t)(row0 + ar) * lda + k0 + ac;
        cp_async16(sA + (uint32_t)(((buf * BM + ar) * 20 + ac) * 4), ap);
        cp_async16(sA + (uint32_t)(((buf * BM + ar + 64) * 20 + ac) * 4),
                   ap + (size_t)64 * lda);
        const int br = tid >> 5;
        const int bc = (tid & 31) << 2;
        const float* bp = Bm + (size_t)(k0 + br) * ldb + col0 + bc;
        cp_async16(sB + (uint32_t)(((buf * BK + br) * (BN + 4) + bc) * 4), bp);
        cp_async16(sB + (uint32_t)(((buf * BK + br + 8) * (BN + 4) + bc) * 4),
                   bp + (size_t)8 * ldb);
        cp_commit();
    };

    float acc[4][4][4];
#pragma unroll
    for (int i = 0; i < 4; i++)
#pragma unroll
        for (int j = 0; j < 4; j++)
#pragma unroll
            for (int r = 0; r < 4; r++) acc[i][j][r] = 0.f;

    const int NITER = K / BK;
    const int NPRE = (STAGES - 1 < NITER) ? STAGES - 1 : NITER;
    for (int p = 0; p < NPRE; p++) issue(p * BK, p);

    for (int it = 0; it < NITER; it++) {
        const int buf = it % STAGES;
        if (it < NITER - 1) {
            asm volatile("cp.async.wait_group %0;\n" :: "n"(STAGES - 2) : "memory");
        } else {
            asm volatile("cp.async.wait_group 0;\n" ::: "memory");
        }
        __syncthreads();
        if (it + STAGES - 1 < NITER)
            issue((it + STAGES - 1) * BK, (it + STAGES - 1) % STAGES);

#pragma unroll
        for (int kk = 0; kk < BK; kk += 8) {
            uint32_t af[4][4];
#pragma unroll
            for (int i = 0; i < 4; i++) {
                const int r = warpRow + i * 16 + (lane >> 2);
                const int c = kk + (lane & 3);
                af[i][0] = __float_as_uint(As[buf][r][c]);
                af[i][1] = __float_as_uint(As[buf][r + 8][c]);
                af[i][2] = __float_as_uint(As[buf][r][c + 4]);
                af[i][3] = __float_as_uint(As[buf][r + 8][c + 4]);
            }
            uint32_t bf[4][2];
#pragma unroll
            for (int j = 0; j < 4; j++) {
                const int n = warpCol + j * 8 + (lane >> 2);
                bf[j][0] = __float_as_uint(Bs[buf][kk + (lane & 3)][n]);
                bf[j][1] = __float_as_uint(Bs[buf][kk + 4 + (lane & 3)][n]);
            }
#pragma unroll
            for (int i = 0; i < 4; i++)
#pragma unroll
                for (int j = 0; j < 4; j++)
                    mma_tf32(acc[i][j], af[i][0], af[i][1], af[i][2], af[i][3],
                             bf[j][0], bf[j][1]);
        }
    }

#pragma unroll
    for (int i = 0; i < 4; i++) {
        const int r = row0 + warpRow + i * 16 + (lane >> 2);
#pragma unroll
        for (int j = 0; j < 4; j++) {
            const int c = col0 + warpCol + j * 8 + 2 * (lane & 3);
            float bb0 = bias ? bias[c] : 0.f;
            float bb1 = bias ? bias[c + 1] : 0.f;
            float v0 = acc[i][j][0] + bb0;
            float v1 = acc[i][j][1] + bb1;
            float v2 = acc[i][j][2] + bb0;
            float v3 = acc[i][j][3] + bb1;
            if (ACT == 1) {
                v0 = 0.5f * v0 * (1.f + erff(v0 * 0.70710678118654752f));
                v1 = 0.5f * v1 * (1.f + erff(v1 * 0.70710678118654752f));
                v2 = 0.5f * v2 * (1.f + erff(v2 * 0.70710678118654752f));
                v3 = 0.5f * v3 * (1.f + erff(v3 * 0.70710678118654752f));
            }
            if (RND) {
                v0 = rnd_tf32(v0); v1 = rnd_tf32(v1);
                v2 = rnd_tf32(v2); v3 = rnd_tf32(v3);
            }
            *(float2*)(C + (size_t)r * ldc + c)       = make_float2(v0, v1);
            *(float2*)(C + (size_t)(r + 8) * ldc + c) = make_float2(v2, v3);
        }
    }
}

// ---------------- elementwise tf32 rounding ----------------------------------
__global__ __launch_bounds__(256) void round_tf32_kernel(
    const float* __restrict__ in, float* __restrict__ out, int n4)
{
    int i = (blockIdx.x * 256 + threadIdx.x);
    if (i < n4) {
        float4 v = ((const float4*)in)[i];
        v.x = rnd_tf32(v.x); v.y = rnd_tf32(v.y);
        v.z = rnd_tf32(v.z); v.w = rnd_tf32(v.w);
        ((float4*)out)[i] = v;
    }
}

// ---------------- row-sum inversion (R3-exact) --------------------------------
__global__ __launch_bounds__(256) void reduce_inv_kernel(
    const float* __restrict__ psum, float* __restrict__ inv)
{
    const int r = blockIdx.x * 256 + threadIdx.x;
    const float* p = psum + (size_t)r * 16;
    float s = 0.f;
#pragma unroll
    for (int i = 0; i < 16; i++) s += p[i];
    inv[r] = 1.0f / s;
}

// ---------------- fused residual add + LayerNorm over D_ = 1024 (R3-exact) ---
__global__ __launch_bounds__(256) void add_ln_kernel(
    const float* __restrict__ a, const float* __restrict__ bres,
    const float* __restrict__ gamma, const float* __restrict__ beta,
    float* __restrict__ out)
{
    const size_t row = blockIdx.x;
    const int tid = threadIdx.x;
    const size_t off = row * D_ + tid * 4;

    float4 va = *(const float4*)(a + off);
    float4 vb = *(const float4*)(bres + off);
    float x0 = va.x + vb.x;
    float x1 = va.y + vb.y;
    float x2 = va.z + vb.z;
    float x3 = va.w + vb.w;

    float s  = x0 + x1 + x2 + x3;
    float sq = x0*x0 + x1*x1 + x2*x2 + x3*x3;
#pragma unroll
    for (int o = 16; o; o >>= 1) {
        s  += __shfl_xor_sync(0xffffffffu, s, o);
        sq += __shfl_xor_sync(0xffffffffu, sq, o);
    }
    __shared__ float rs[8];
    __shared__ float rq[8];
    if ((tid & 31) == 0) { rs[tid >> 5] = s; rq[tid >> 5] = sq; }
    __syncthreads();
    s = 0.f; sq = 0.f;
#pragma unroll
    for (int w = 0; w < 8; w++) { s += rs[w]; sq += rq[w]; }

    const float mu  = s * (1.0f / D_);
    const float var = sq * (1.0f / D_) - mu * mu;
    const float inv = rsqrtf(var + 1e-5f);

    float4 g  = *(const float4*)(gamma + tid * 4);
    float4 bt = *(const float4*)(beta + tid * 4);
    float4 o4;
    o4.x = (x0 - mu) * inv * g.x + bt.x;
    o4.y = (x1 - mu) * inv * g.y + bt.y;
    o4.z = (x2 - mu) * inv * g.z + bt.z;
    o4.w = (x3 - mu) * inv * g.w + bt.w;
    *(float4*)(out + off) = o4;
}

// ---------------- launch ----------------------------------------------------
extern "C" void kernel_launch(void* const* d_in, const int* in_sizes, int n_in,
                              void* d_out, int out_size)
{
    const float* x     = (const float*)d_in[0];
    const float* Wq    = (const float*)d_in[1];
    const float* bq    = (const float*)d_in[2];
    const float* Wk    = (const float*)d_in[3];
    const float* bk    = (const float*)d_in[4];
    const float* Wv    = (const float*)d_in[5];
    const float* bv    = (const float*)d_in[6];
    const float* Wo    = (const float*)d_in[7];
    const float* bo    = (const float*)d_in[8];
    const float* W1    = (const float*)d_in[9];
    const float* b1    = (const float*)d_in[10];
    const float* W2    = (const float*)d_in[11];
    const float* b2    = (const float*)d_in[12];
    const float* gamma = (const float*)d_in[13];
    const float* beta  = (const float*)d_in[14];

    float* out  = (float*)d_out;
    float* attn = out + (size_t)B_ * S_ * D_;

    float *q, *k, *v, *ao, *t1, *h, *hid, *psum, *ginv;
    float *xr, *wv, *wo, *w1, *w2, *aor, *hr;
    cudaGetSymbolAddress((void**)&q,    g_q);
    cudaGetSymbolAddress((void**)&k,    g_k);
    cudaGetSymbolAddress((void**)&v,    g_v);
    cudaGetSymbolAddress((void**)&ao,   g_ao);
    cudaGetSymbolAddress((void**)&t1,   g_t1);
    cudaGetSymbolAddress((void**)&h,    g_h);
    cudaGetSymbolAddress((void**)&hid,  g_hid);
    cudaGetSymbolAddress((void**)&psum, g_psum);
    cudaGetSymbolAddress((void**)&ginv, g_inv);
    cudaGetSymbolAddress((void**)&xr,   g_xr);
    cudaGetSymbolAddress((void**)&wv,   g_wv);
    cudaGetSymbolAddress((void**)&wo,   g_wo);
    cudaGetSymbolAddress((void**)&w1,   g_w1);
    cudaGetSymbolAddress((void**)&w2,   g_w2);
    cudaGetSymbolAddress((void**)&aor,  g_aor);
    cudaGetSymbolAddress((void**)&hr,   g_hr);

    dim3 blk(256);
    auto rconv = [&](const float* src, float* dst, size_t n) {
        int n4 = (int)(n / 4);
        round_tf32_kernel<<<(n4 + 255) / 256, blk>>>(src, dst, n4);
    };

    // pre-round fast-path operands (launches 1-5)
    rconv(x,  xr, (size_t)M_ * D_);
    rconv(Wv, wv, (size_t)D_ * D_);
    rconv(Wo, wo, (size_t)D_ * D_);
    rconv(W1, w1, (size_t)D_ * HID_);
    rconv(W2, w2, (size_t)HID_ * D_);

    // attn-critical path: R3-exact kernels on raw x/Wq/Wk
    tf32_gemm<128,0,0><<<dim3(D_/128, M_/128), blk>>>(x, Wq, bq, nullptr, nullptr, q,
                                                      M_, D_, D_, D_, D_, D_);   // 6 <- ncu
    tf32_gemm<128,0,0><<<dim3(D_/128, M_/128), blk>>>(x, Wk, bk, nullptr, nullptr, k,
                                                      M_, D_, D_, D_, D_, D_);   // 7

    // v projection (fast path; out0-only)
    fgemm<0,0><<<dim3(D_/128, M_/128), blk>>>(xr, wv, bv, v, M_, D_, D_, D_, D_, D_);

    // energy -> exp(e/8) into attn (unnormalized) + row partial sums (R3-exact)
    tf32_gemm<128,1,0><<<dim3(S_/128, S_/128, B_*H_), blk>>>(q, k, nullptr, nullptr,
                                                             psum, attn,
                                                             S_, S_, DH_, D_, D_, S_);
    reduce_inv_kernel<<<NROWS_/256, blk>>>(psum, ginv);

    // AV: O = inv * (P' @ V); normalizes attn in-place (R3-exact)
    tf32_gemm<64,2,0><<<dim3(1, S_/128, B_*H_), blk>>>(attn, v, nullptr, ginv,
                                                       attn, ao,
                                                       S_, DH_, S_, S_, D_, D_);

    // output projection + residual + LN (fast path)
    rconv(ao, aor, (size_t)M_ * D_);
    fgemm<0,0><<<dim3(D_/128, M_/128), blk>>>(aor, wo, bo, t1, M_, D_, D_, D_, D_, D_);
    add_ln_kernel<<<M_, blk>>>(x, t1, gamma, beta, h);

    // MLP (fast path)
    rconv(h, hr, (size_t)M_ * D_);
    fgemm<1,1><<<dim3(HID_/128, M_/128), blk>>>(hr, w1, b1, hid, M_, HID_, D_, D_, HID_, HID_);
    fgemm<0,0><<<dim3(D_/128, M_/128), blk>>>(hid, w2, b2, t1, M_, D_, HID_, HID_, D_, D_);
    add_ln_kernel<<<M_, blk>>>(t1, h, gamma, beta, out);
}